// round 2
// baseline (speedup 1.0000x reference)
#include <cuda_runtime.h>
#include <cuda_bf16.h>
#include <cstdint>

// Problem constants (match reference)
#define N_NODES   100000
#define N_EDGES   400000
#define N_GRAPHS  2000
#define NODE_F    78
#define HID       128
#define MAXW      256   // widest feature dim

// Scratch buffers (device globals: allocation-free rule)
__device__ float g_bufA[(size_t)N_NODES * MAXW];  // layer input / finalize output
__device__ float g_bufB[(size_t)N_NODES * MAXW];  // g = (X@W)*dinv  (gather source)
__device__ float g_bufC[(size_t)N_NODES * MAXW];  // acc (scatter destination)
__device__ float g_deg [N_NODES];
__device__ float g_dinv[N_NODES];
__device__ float g_pool[N_GRAPHS * HID];
__device__ float g_cnt [N_GRAPHS];

// ---------------------------------------------------------------------------
// degree / norm
// ---------------------------------------------------------------------------
__global__ void k_deg_init(float* deg, int n) {
    int i = blockIdx.x * blockDim.x + threadIdx.x;
    if (i < n) deg[i] = 1.0f;  // self-loop
}

__global__ void k_deg_count(const int* __restrict__ ei, float* deg, int E) {
    int e = blockIdx.x * blockDim.x + threadIdx.x;
    if (e < E) {
        int d = ei[E + e];  // dst row
        atomicAdd(&deg[d], 1.0f);
    }
}

__global__ void k_dinv(const float* __restrict__ deg, float* dinv, int n) {
    int i = blockIdx.x * blockDim.x + threadIdx.x;
    if (i < n) dinv[i] = rsqrtf(deg[i]);
}

// ---------------------------------------------------------------------------
// Tiled SGEMM with fused dinv row-scale, dual-write epilogue (g and acc).
// BM=64 (nodes) x BN=128 (out cols) x BK=16, 256 threads, per-thread 8x4 tile.
// grid.y covers O/128 column blocks.
// ---------------------------------------------------------------------------
__global__ __launch_bounds__(256, 2)
void k_gemm_scale(const float* __restrict__ X, const float* __restrict__ W,
                  const float* __restrict__ dinv,
                  float* __restrict__ g, float* __restrict__ acc,
                  int N, int K, int O) {
    __shared__ float As[64][16];
    __shared__ float Bs[16][128];

    const int tid = threadIdx.x;
    const int tx  = tid & 31;   // column group (N dim of tile)
    const int ty  = tid >> 5;   // row group    (M dim of tile)
    const int row0 = blockIdx.x * 64;
    const int ob   = blockIdx.y * 128;

    float accr[8][4];
#pragma unroll
    for (int m = 0; m < 8; m++)
#pragma unroll
        for (int n = 0; n < 4; n++) accr[m][n] = 0.0f;

    const int ar = tid >> 2;          // A load: row within tile (0..63)
    const int ac = (tid & 3) * 4;     // A load: k offset (0,4,8,12)
    const int grow = row0 + ar;

    for (int kk = 0; kk < K; kk += 16) {
#pragma unroll
        for (int i = 0; i < 4; i++) {
            int k = kk + ac + i;
            As[ar][ac + i] = (grow < N && k < K) ? X[(size_t)grow * K + k] : 0.0f;
        }
#pragma unroll
        for (int i = 0; i < 8; i++) {
            int e  = i * 256 + tid;
            int bk = e >> 7;
            int bo = e & 127;
            int k  = kk + bk;
            Bs[bk][bo] = (k < K) ? W[(size_t)k * O + ob + bo] : 0.0f;
        }
        __syncthreads();

#pragma unroll
        for (int k = 0; k < 16; k++) {
            float4 b4 = *reinterpret_cast<const float4*>(&Bs[k][tx * 4]);
#pragma unroll
            for (int m = 0; m < 8; m++) {
                float a = As[ty * 8 + m][k];
                accr[m][0] += a * b4.x;
                accr[m][1] += a * b4.y;
                accr[m][2] += a * b4.z;
                accr[m][3] += a * b4.w;
            }
        }
        __syncthreads();
    }

#pragma unroll
    for (int m = 0; m < 8; m++) {
        int row = row0 + ty * 8 + m;
        if (row < N) {
            float d = dinv[row];
            float4 v = make_float4(accr[m][0] * d, accr[m][1] * d,
                                   accr[m][2] * d, accr[m][3] * d);
            size_t off = (size_t)row * O + ob + tx * 4;
            *reinterpret_cast<float4*>(g + off)   = v;  // gather source
            *reinterpret_cast<float4*>(acc + off) = v;  // self-loop term
        }
    }
}

// ---------------------------------------------------------------------------
// Edge scatter: one warp per edge. acc[dst] += g[src]
// ---------------------------------------------------------------------------
__global__ void k_scatter(const float* __restrict__ g, const int* __restrict__ ei,
                          float* __restrict__ acc, int E, int O) {
    int gt   = blockIdx.x * blockDim.x + threadIdx.x;
    int warp = gt >> 5;
    int lane = gt & 31;
    if (warp >= E) return;
    int s = ei[warp];
    int d = ei[E + warp];
    const float* gp = g   + (size_t)s * O;
    float*       ap = acc + (size_t)d * O;
    for (int c = lane * 4; c < O; c += 128) {
        float4 v = *reinterpret_cast<const float4*>(gp + c);
        atomicAdd(ap + c + 0, v.x);
        atomicAdd(ap + c + 1, v.y);
        atomicAdd(ap + c + 2, v.z);
        atomicAdd(ap + c + 3, v.w);
    }
}

// ---------------------------------------------------------------------------
// out = relu(dinv[row] * acc + bias[col])
// ---------------------------------------------------------------------------
__global__ void k_finalize(const float* __restrict__ acc, const float* __restrict__ b,
                           const float* __restrict__ dinv, float* __restrict__ out,
                           int N, int O) {
    size_t idx = (size_t)blockIdx.x * blockDim.x + threadIdx.x;
    size_t total = (size_t)N * O;
    if (idx >= total) return;
    int row = (int)(idx / O);
    int col = (int)(idx % O);
    float v = acc[idx] * dinv[row] + b[col];
    out[idx] = fmaxf(v, 0.0f);
}

// ---------------------------------------------------------------------------
// Pooling
// ---------------------------------------------------------------------------
__global__ void k_pool_zero(float* pool, float* cnt) {
    int i = blockIdx.x * blockDim.x + threadIdx.x;
    if (i < N_GRAPHS * HID) pool[i] = 0.0f;
    if (i < N_GRAPHS)       cnt[i]  = 0.0f;
}

__global__ void k_pool_accum(const float* __restrict__ feat, const int* __restrict__ batch,
                             float* __restrict__ pool, float* __restrict__ cnt, int N) {
    int gt   = blockIdx.x * blockDim.x + threadIdx.x;
    int node = gt >> 5;
    int lane = gt & 31;
    if (node >= N) return;
    int gph = batch[node];
    float4 v = *reinterpret_cast<const float4*>(feat + (size_t)node * HID + lane * 4);
    float* p = pool + (size_t)gph * HID + lane * 4;
    atomicAdd(p + 0, v.x);
    atomicAdd(p + 1, v.y);
    atomicAdd(p + 2, v.z);
    atomicAdd(p + 3, v.w);
    if (lane == 0) atomicAdd(&cnt[gph], 1.0f);
}

// ---------------------------------------------------------------------------
// Final MLP: relu(mean @ fw1 + fb1) @ fw2 + fb2. One block (64 threads) / graph.
// ---------------------------------------------------------------------------
__global__ void k_mlp(const float* __restrict__ pool, const float* __restrict__ cnt,
                      const float* __restrict__ fw1, const float* __restrict__ fb1,
                      const float* __restrict__ fw2, const float* __restrict__ fb2,
                      float* __restrict__ out) {
    int g = blockIdx.x;
    int t = threadIdx.x;  // 0..63
    __shared__ float sh[64];
    float inv = 1.0f / fmaxf(cnt[g], 1.0f);
    float s = fb1[t];
#pragma unroll 4
    for (int k = 0; k < HID; k++) {
        s += pool[(size_t)g * HID + k] * inv * fw1[k * 64 + t];
    }
    float h = fmaxf(s, 0.0f);
    sh[t] = h * fw2[t];
    __syncthreads();
    if (t == 0) {
        float r = 0.0f;
#pragma unroll
        for (int i = 0; i < 64; i++) r += sh[i];
        out[g] = r + fb2[0];
    }
}

// ---------------------------------------------------------------------------
// launch
// ---------------------------------------------------------------------------
extern "C" void kernel_launch(void* const* d_in, const int* in_sizes, int n_in,
                              void* d_out, int out_size) {
    const float* x   = (const float*)d_in[0];
    const int*   ei  = (const int*)d_in[1];
    const int*   bat = (const int*)d_in[2];
    const float* W1 = (const float*)d_in[3];
    const float* b1 = (const float*)d_in[4];
    const float* W2 = (const float*)d_in[5];
    const float* b2 = (const float*)d_in[6];
    const float* W3 = (const float*)d_in[7];
    const float* b3 = (const float*)d_in[8];
    const float* fw1 = (const float*)d_in[9];
    const float* fb1 = (const float*)d_in[10];
    const float* fw2 = (const float*)d_in[11];
    const float* fb2 = (const float*)d_in[12];
    float* out = (float*)d_out;

    const int N = N_NODES;
    const int E = in_sizes[1] / 2;  // 400000

    float* bufA; cudaGetSymbolAddress((void**)&bufA, g_bufA);
    float* bufB; cudaGetSymbolAddress((void**)&bufB, g_bufB);
    float* bufC; cudaGetSymbolAddress((void**)&bufC, g_bufC);
    float* deg;  cudaGetSymbolAddress((void**)&deg,  g_deg);
    float* dinv; cudaGetSymbolAddress((void**)&dinv, g_dinv);
    float* pool; cudaGetSymbolAddress((void**)&pool, g_pool);
    float* cnt;  cudaGetSymbolAddress((void**)&cnt,  g_cnt);

    // degree / normalization
    k_deg_init <<<(N + 255) / 256, 256>>>(deg, N);
    k_deg_count<<<(E + 255) / 256, 256>>>(ei, deg, E);
    k_dinv     <<<(N + 255) / 256, 256>>>(deg, dinv, N);

    const int gemm_mblocks = (N + 63) / 64;
    const int scat_blocks  = (E * 32 + 255) / 256;

    // ---- Layer 1: 78 -> 128 ----
    {
        dim3 grid(gemm_mblocks, 1);
        k_gemm_scale<<<grid, 256>>>(x, W1, dinv, bufB, bufC, N, NODE_F, HID);
        k_scatter<<<scat_blocks, 256>>>(bufB, ei, bufC, E, HID);
        k_finalize<<<((size_t)N * HID + 255) / 256, 256>>>(bufC, b1, dinv, bufA, N, HID);
    }
    // ---- Layer 2: 128 -> 256 ----
    {
        dim3 grid(gemm_mblocks, 2);
        k_gemm_scale<<<grid, 256>>>(bufA, W2, dinv, bufB, bufC, N, HID, 2 * HID);
        k_scatter<<<scat_blocks, 256>>>(bufB, ei, bufC, E, 2 * HID);
        k_finalize<<<((size_t)N * 2 * HID + 255) / 256, 256>>>(bufC, b2, dinv, bufA, N, 2 * HID);
    }
    // ---- Layer 3: 256 -> 128 ----
    {
        dim3 grid(gemm_mblocks, 1);
        k_gemm_scale<<<grid, 256>>>(bufA, W3, dinv, bufB, bufC, N, 2 * HID, HID);
        k_scatter<<<scat_blocks, 256>>>(bufB, ei, bufC, E, HID);
        k_finalize<<<((size_t)N * HID + 255) / 256, 256>>>(bufC, b3, dinv, bufA, N, HID);
    }

    // ---- Pool + MLP ----
    k_pool_zero <<<(N_GRAPHS * HID + 255) / 256, 256>>>(pool, cnt);
    k_pool_accum<<<((size_t)N * 32 + 255) / 256, 256>>>(bufA, bat, pool, cnt, N);
    k_mlp<<<N_GRAPHS, 64>>>(pool, cnt, fw1, fb1, fw2, fb2, out);
}

// round 3
// speedup vs baseline: 1.7906x; 1.7906x over previous
#include <cuda_runtime.h>
#include <cuda_bf16.h>
#include <cstdint>

#define N_NODES   100000
#define N_EDGES   400000
#define N_GRAPHS  2000
#define NODE_F    78
#define HID       128
#define MAXW      256
#define SCAN_B    256

// Scratch (device globals: allocation-free rule)
__device__ float g_bufA[(size_t)N_NODES * MAXW];   // layer input / output
__device__ float g_bufB[(size_t)N_NODES * MAXW];   // g = (X@W)*dinv (gather source)
__device__ float g_dinv[N_NODES];
__device__ float g_pool[N_GRAPHS * HID];
__device__ float g_cnt [N_GRAPHS];
__device__ int   g_indeg [N_NODES];
__device__ int   g_excl  [N_NODES];
__device__ int   g_bsum  [512];
__device__ int   g_rowptr[N_NODES + 1];
__device__ int   g_cursor[N_NODES];
__device__ int   g_col   [N_EDGES];

// ---------------------------------------------------------------------------
// CSR build: indeg -> exclusive scan -> fill
// ---------------------------------------------------------------------------
__global__ void k_indeg_zero(int* indeg, int n) {
    int i = blockIdx.x * blockDim.x + threadIdx.x;
    if (i < n) indeg[i] = 0;
}

__global__ void k_indeg_count(const int* __restrict__ ei, int* indeg, int E) {
    int e = blockIdx.x * blockDim.x + threadIdx.x;
    if (e < E) atomicAdd(&indeg[ei[E + e]], 1);
}

// dinv from indeg (+1 self-loop)
__global__ void k_dinv(const int* __restrict__ indeg, float* dinv, int n) {
    int i = blockIdx.x * blockDim.x + threadIdx.x;
    if (i < n) dinv[i] = rsqrtf((float)indeg[i] + 1.0f);
}

__global__ void k_scan1(const int* __restrict__ in, int* out, int* bsum, int n) {
    __shared__ int sh[SCAN_B];
    int i = blockIdx.x * SCAN_B + threadIdx.x;
    int v = (i < n) ? in[i] : 0;
    sh[threadIdx.x] = v;
    __syncthreads();
#pragma unroll
    for (int off = 1; off < SCAN_B; off <<= 1) {
        int t = (threadIdx.x >= off) ? sh[threadIdx.x - off] : 0;
        __syncthreads();
        sh[threadIdx.x] += t;
        __syncthreads();
    }
    if (i < n) out[i] = sh[threadIdx.x] - v;  // exclusive within block
    if (threadIdx.x == SCAN_B - 1) bsum[blockIdx.x] = sh[threadIdx.x];
}

__global__ void k_scan2(int* bsum, int nb) {  // single block, nb <= 512
    __shared__ int sh[512];
    int t = threadIdx.x;
    int v = (t < nb) ? bsum[t] : 0;
    sh[t] = v;
    __syncthreads();
#pragma unroll
    for (int off = 1; off < 512; off <<= 1) {
        int x = (t >= off) ? sh[t - off] : 0;
        __syncthreads();
        sh[t] += x;
        __syncthreads();
    }
    if (t < nb) bsum[t] = sh[t] - v;  // exclusive
}

__global__ void k_scan3(int* rowptr, int* cursor, const int* __restrict__ excl,
                        const int* __restrict__ bsum, int n, int E) {
    int i = blockIdx.x * blockDim.x + threadIdx.x;
    if (i < n) {
        int v = excl[i] + bsum[i / SCAN_B];
        rowptr[i] = v;
        cursor[i] = v;
    }
    if (i == 0) rowptr[n] = E;
}

__global__ void k_fill(const int* __restrict__ ei, int* cursor, int* colarr, int E) {
    int e = blockIdx.x * blockDim.x + threadIdx.x;
    if (e < E) {
        int s = ei[e];
        int d = ei[E + e];
        int p = atomicAdd(&cursor[d], 1);
        colarr[p] = s;
    }
}

// ---------------------------------------------------------------------------
// Tiled SGEMM with fused dinv row-scale. BM=64 x BN=128 x BK=16, 256 thr.
// ---------------------------------------------------------------------------
__global__ __launch_bounds__(256, 2)
void k_gemm_scale(const float* __restrict__ X, const float* __restrict__ W,
                  const float* __restrict__ dinv, float* __restrict__ g,
                  int N, int K, int O) {
    __shared__ float As[64][16];
    __shared__ float Bs[16][128];

    const int tid = threadIdx.x;
    const int tx  = tid & 31;
    const int ty  = tid >> 5;
    const int row0 = blockIdx.x * 64;
    const int ob   = blockIdx.y * 128;

    float accr[8][4];
#pragma unroll
    for (int m = 0; m < 8; m++)
#pragma unroll
        for (int n = 0; n < 4; n++) accr[m][n] = 0.0f;

    const int ar = tid >> 2;
    const int ac = (tid & 3) * 4;
    const int grow = row0 + ar;

    for (int kk = 0; kk < K; kk += 16) {
#pragma unroll
        for (int i = 0; i < 4; i++) {
            int k = kk + ac + i;
            As[ar][ac + i] = (grow < N && k < K) ? X[(size_t)grow * K + k] : 0.0f;
        }
#pragma unroll
        for (int i = 0; i < 8; i++) {
            int e  = i * 256 + tid;
            int bk = e >> 7;
            int bo = e & 127;
            int k  = kk + bk;
            Bs[bk][bo] = (k < K) ? W[(size_t)k * O + ob + bo] : 0.0f;
        }
        __syncthreads();

#pragma unroll
        for (int k = 0; k < 16; k++) {
            float4 b4 = *reinterpret_cast<const float4*>(&Bs[k][tx * 4]);
#pragma unroll
            for (int m = 0; m < 8; m++) {
                float a = As[ty * 8 + m][k];
                accr[m][0] += a * b4.x;
                accr[m][1] += a * b4.y;
                accr[m][2] += a * b4.z;
                accr[m][3] += a * b4.w;
            }
        }
        __syncthreads();
    }

#pragma unroll
    for (int m = 0; m < 8; m++) {
        int row = row0 + ty * 8 + m;
        if (row < N) {
            float d = dinv[row];
            float4 v = make_float4(accr[m][0] * d, accr[m][1] * d,
                                   accr[m][2] * d, accr[m][3] * d);
            *reinterpret_cast<float4*>(g + (size_t)row * O + ob + tx * 4) = v;
        }
    }
}

// ---------------------------------------------------------------------------
// Aggregate (gather by destination) + finalize fused:
//   out[d] = relu( dinv[d] * ( g[d] + sum_{s in N(d)} g[s] ) + bias )
// One warp per node, float4 per lane.
// ---------------------------------------------------------------------------
__global__ void k_aggregate128(const float* __restrict__ g,
                               const int* __restrict__ rowptr,
                               const int* __restrict__ colarr,
                               const float* __restrict__ dinv,
                               const float* __restrict__ bias,
                               float* __restrict__ out, int N) {
    int warp = (blockIdx.x * blockDim.x + threadIdx.x) >> 5;
    int lane = threadIdx.x & 31;
    if (warp >= N) return;
    int beg = rowptr[warp], end = rowptr[warp + 1];
    int c = lane * 4;
    float4 a = *reinterpret_cast<const float4*>(g + (size_t)warp * 128 + c);  // self-loop
    for (int e = beg; e < end; e++) {
        int s = colarr[e];
        float4 v = *reinterpret_cast<const float4*>(g + (size_t)s * 128 + c);
        a.x += v.x; a.y += v.y; a.z += v.z; a.w += v.w;
    }
    float dv = dinv[warp];
    float4 b4 = *reinterpret_cast<const float4*>(bias + c);
    float4 r = make_float4(fmaxf(a.x * dv + b4.x, 0.0f),
                           fmaxf(a.y * dv + b4.y, 0.0f),
                           fmaxf(a.z * dv + b4.z, 0.0f),
                           fmaxf(a.w * dv + b4.w, 0.0f));
    *reinterpret_cast<float4*>(out + (size_t)warp * 128 + c) = r;
}

__global__ void k_aggregate256(const float* __restrict__ g,
                               const int* __restrict__ rowptr,
                               const int* __restrict__ colarr,
                               const float* __restrict__ dinv,
                               const float* __restrict__ bias,
                               float* __restrict__ out, int N) {
    int warp = (blockIdx.x * blockDim.x + threadIdx.x) >> 5;
    int lane = threadIdx.x & 31;
    if (warp >= N) return;
    int beg = rowptr[warp], end = rowptr[warp + 1];
    int c0 = lane * 4, c1 = c0 + 128;
    const float* self = g + (size_t)warp * 256;
    float4 a0 = *reinterpret_cast<const float4*>(self + c0);
    float4 a1 = *reinterpret_cast<const float4*>(self + c1);
    for (int e = beg; e < end; e++) {
        int s = colarr[e];
        const float* gp = g + (size_t)s * 256;
        float4 v0 = *reinterpret_cast<const float4*>(gp + c0);
        float4 v1 = *reinterpret_cast<const float4*>(gp + c1);
        a0.x += v0.x; a0.y += v0.y; a0.z += v0.z; a0.w += v0.w;
        a1.x += v1.x; a1.y += v1.y; a1.z += v1.z; a1.w += v1.w;
    }
    float dv = dinv[warp];
    float4 b0 = *reinterpret_cast<const float4*>(bias + c0);
    float4 b1 = *reinterpret_cast<const float4*>(bias + c1);
    float* op = out + (size_t)warp * 256;
    *reinterpret_cast<float4*>(op + c0) =
        make_float4(fmaxf(a0.x * dv + b0.x, 0.0f), fmaxf(a0.y * dv + b0.y, 0.0f),
                    fmaxf(a0.z * dv + b0.z, 0.0f), fmaxf(a0.w * dv + b0.w, 0.0f));
    *reinterpret_cast<float4*>(op + c1) =
        make_float4(fmaxf(a1.x * dv + b1.x, 0.0f), fmaxf(a1.y * dv + b1.y, 0.0f),
                    fmaxf(a1.z * dv + b1.z, 0.0f), fmaxf(a1.w * dv + b1.w, 0.0f));
}

// ---------------------------------------------------------------------------
// Pooling + MLP
// ---------------------------------------------------------------------------
__global__ void k_pool_zero(float* pool, float* cnt) {
    int i = blockIdx.x * blockDim.x + threadIdx.x;
    if (i < N_GRAPHS * HID) pool[i] = 0.0f;
    if (i < N_GRAPHS)       cnt[i]  = 0.0f;
}

__global__ void k_pool_accum(const float* __restrict__ feat, const int* __restrict__ batch,
                             float* __restrict__ pool, float* __restrict__ cnt, int N) {
    int gt   = blockIdx.x * blockDim.x + threadIdx.x;
    int node = gt >> 5;
    int lane = gt & 31;
    if (node >= N) return;
    int gph = batch[node];
    float4 v = *reinterpret_cast<const float4*>(feat + (size_t)node * HID + lane * 4);
    float* p = pool + (size_t)gph * HID + lane * 4;
    atomicAdd(p + 0, v.x);
    atomicAdd(p + 1, v.y);
    atomicAdd(p + 2, v.z);
    atomicAdd(p + 3, v.w);
    if (lane == 0) atomicAdd(&cnt[gph], 1.0f);
}

__global__ void k_mlp(const float* __restrict__ pool, const float* __restrict__ cnt,
                      const float* __restrict__ fw1, const float* __restrict__ fb1,
                      const float* __restrict__ fw2, const float* __restrict__ fb2,
                      float* __restrict__ out) {
    int g = blockIdx.x;
    int t = threadIdx.x;  // 0..63
    __shared__ float sh[64];
    float inv = 1.0f / fmaxf(cnt[g], 1.0f);
    float s = fb1[t];
#pragma unroll 4
    for (int k = 0; k < HID; k++) {
        s += pool[(size_t)g * HID + k] * inv * fw1[k * 64 + t];
    }
    float h = fmaxf(s, 0.0f);
    sh[t] = h * fw2[t];
    __syncthreads();
    if (t == 0) {
        float r = 0.0f;
#pragma unroll
        for (int i = 0; i < 64; i++) r += sh[i];
        out[g] = r + fb2[0];
    }
}

// ---------------------------------------------------------------------------
// launch
// ---------------------------------------------------------------------------
extern "C" void kernel_launch(void* const* d_in, const int* in_sizes, int n_in,
                              void* d_out, int out_size) {
    const float* x   = (const float*)d_in[0];
    const int*   ei  = (const int*)d_in[1];
    const int*   bat = (const int*)d_in[2];
    const float* W1 = (const float*)d_in[3];
    const float* b1 = (const float*)d_in[4];
    const float* W2 = (const float*)d_in[5];
    const float* b2 = (const float*)d_in[6];
    const float* W3 = (const float*)d_in[7];
    const float* b3 = (const float*)d_in[8];
    const float* fw1 = (const float*)d_in[9];
    const float* fb1 = (const float*)d_in[10];
    const float* fw2 = (const float*)d_in[11];
    const float* fb2 = (const float*)d_in[12];
    float* out = (float*)d_out;

    const int N = N_NODES;
    const int E = in_sizes[1] / 2;

    float* bufA; cudaGetSymbolAddress((void**)&bufA, g_bufA);
    float* bufB; cudaGetSymbolAddress((void**)&bufB, g_bufB);
    float* dinv; cudaGetSymbolAddress((void**)&dinv, g_dinv);
    float* pool; cudaGetSymbolAddress((void**)&pool, g_pool);
    float* cnt;  cudaGetSymbolAddress((void**)&cnt,  g_cnt);
    int* indeg;  cudaGetSymbolAddress((void**)&indeg,  g_indeg);
    int* excl;   cudaGetSymbolAddress((void**)&excl,   g_excl);
    int* bsum;   cudaGetSymbolAddress((void**)&bsum,   g_bsum);
    int* rowptr; cudaGetSymbolAddress((void**)&rowptr, g_rowptr);
    int* cursor; cudaGetSymbolAddress((void**)&cursor, g_cursor);
    int* colarr; cudaGetSymbolAddress((void**)&colarr, g_col);

    // ---- CSR build + norm ----
    const int nb = (N + SCAN_B - 1) / SCAN_B;  // 391
    k_indeg_zero <<<nb, SCAN_B>>>(indeg, N);
    k_indeg_count<<<(E + 255) / 256, 256>>>(ei, indeg, E);
    k_dinv       <<<nb, SCAN_B>>>(indeg, dinv, N);
    k_scan1      <<<nb, SCAN_B>>>(indeg, excl, bsum, N);
    k_scan2      <<<1, 512>>>(bsum, nb);
    k_scan3      <<<nb, SCAN_B>>>(rowptr, cursor, excl, bsum, N, E);
    k_fill       <<<(E + 255) / 256, 256>>>(ei, cursor, colarr, E);

    const int gemm_mblocks = (N + 63) / 64;
    const int agg_blocks   = (N * 32 + 255) / 256;

    // ---- Layer 1: 78 -> 128 ----
    k_gemm_scale<<<dim3(gemm_mblocks, 1), 256>>>(x, W1, dinv, bufB, N, NODE_F, HID);
    k_aggregate128<<<agg_blocks, 256>>>(bufB, rowptr, colarr, dinv, b1, bufA, N);

    // ---- Layer 2: 128 -> 256 ----
    k_gemm_scale<<<dim3(gemm_mblocks, 2), 256>>>(bufA, W2, dinv, bufB, N, HID, 2 * HID);
    k_aggregate256<<<agg_blocks, 256>>>(bufB, rowptr, colarr, dinv, b2, bufA, N);

    // ---- Layer 3: 256 -> 128 ----
    k_gemm_scale<<<dim3(gemm_mblocks, 1), 256>>>(bufA, W3, dinv, bufB, N, 2 * HID, HID);
    k_aggregate128<<<agg_blocks, 256>>>(bufB, rowptr, colarr, dinv, b3, bufA, N);

    // ---- Pool + MLP ----
    k_pool_zero <<<(N_GRAPHS * HID + 255) / 256, 256>>>(pool, cnt);
    k_pool_accum<<<(N * 32 + 255) / 256, 256>>>(bufA, bat, pool, cnt, N);
    k_mlp<<<N_GRAPHS, 64>>>(pool, cnt, fw1, fb1, fw2, fb2, out);
}